// round 7
// baseline (speedup 1.0000x reference)
#include <cuda_runtime.h>
#include <cuda_bf16.h>
#include <stdint.h>
#include <math.h>

#define FEAT  512
#define NCLS  100000
#define NROW  512
#define BM    128
#define BN    128
#define NCT   782             // class tiles (782*128 = 100096 padded)
#define NRT   4               // row tiles
#define CTP   782
#define NCH   8               // K chunks of 64

#define C_COS_M   0.87758256189037276f
#define C_SIN_M   0.47942553860420301f
#define C_THRESH  (-0.87758256189037276f)
#define C_MM      0.23971276930210156f
#define C_S       64.0f
#define C_EPS     0.1f

// ---- scratch ----
__device__ float          g_e[NROW * FEAT];
__device__ __nv_bfloat16  g_ebf[NROW * FEAT];
__device__ float g_tl[NROW];
__device__ float g_ctm[NROW];
__device__ float g_ft[NROW];
__device__ float g_t;
__device__ float g_pm[NROW * CTP];
__device__ float g_ps[NROW * CTP];
__device__ float g_psl[NROW * CTP];
__device__ float g_rowloss[NROW];

// =================== helpers ===================
__device__ __forceinline__ void cp16(uint32_t dst, const void* src) {
    asm volatile("cp.async.cg.shared.global [%0], [%1], 16;" :: "r"(dst), "l"(src));
}
__device__ __forceinline__ void cp16z(uint32_t dst, const void* src, int nbytes) {
    asm volatile("cp.async.cg.shared.global [%0], [%1], 16, %2;"
                 :: "r"(dst), "l"(src), "r"(nbytes));
}
__device__ __forceinline__ uint32_t s2u(const void* p) {
    uint32_t a;
    asm("{ .reg .u64 t; cvta.to.shared.u64 t, %1; cvt.u32.u64 %0, t; }" : "=r"(a) : "l"(p));
    return a;
}
__device__ __forceinline__ uint32_t sw(uint32_t x) { return x ^ ((x >> 3) & 0x70); }
__device__ __forceinline__ void ldsm4(uint32_t* a, uint32_t addr) {
    asm volatile("ldmatrix.sync.aligned.m8n8.x4.shared.b16 {%0,%1,%2,%3}, [%4];"
                 : "=r"(a[0]), "=r"(a[1]), "=r"(a[2]), "=r"(a[3]) : "r"(addr));
}
__device__ __forceinline__ void mma16816(float* c, const uint32_t* a, const uint32_t* b) {
    asm volatile(
        "mma.sync.aligned.m16n8k16.row.col.f32.bf16.bf16.f32 "
        "{%0,%1,%2,%3}, {%4,%5,%6,%7}, {%8,%9}, {%0,%1,%2,%3};"
        : "+f"(c[0]), "+f"(c[1]), "+f"(c[2]), "+f"(c[3])
        : "r"(a[0]), "r"(a[1]), "r"(a[2]), "r"(a[3]), "r"(b[0]), "r"(b[1]));
}

// =================== K1: row-normalize e ===================
__global__ void k_norm_e(const float* __restrict__ emb) {
    int r = blockIdx.x, t = threadIdx.x;   // 512 x 128
    float v[4], s = 0.f;
#pragma unroll
    for (int i = 0; i < 4; i++) { v[i] = emb[r * FEAT + t + i * 128]; s += v[i] * v[i]; }
#pragma unroll
    for (int o = 16; o; o >>= 1) s += __shfl_xor_sync(0xffffffffu, s, o);
    __shared__ float sm[4];
    if ((t & 31) == 0) sm[t >> 5] = s;
    __syncthreads();
    float inv = rsqrtf(sm[0] + sm[1] + sm[2] + sm[3]);
#pragma unroll
    for (int i = 0; i < 4; i++) {
        float x = v[i] * inv;
        g_e[r * FEAT + t + i * 128] = x;
        g_ebf[r * FEAT + t + i * 128] = __float2bfloat16(x);
    }
}

// =================== K2: target logits + ctm/ft (self-normalizing) ===================
__global__ void k_target(const float* __restrict__ w, const int* __restrict__ label) {
    int gw = (blockIdx.x * blockDim.x + threadIdx.x) >> 5;  // 64 x 256 -> 512 warps
    int lane = threadIdx.x & 31;
    if (gw >= NROW) return;
    int lab = label[gw];
    const float* e = g_e + gw * FEAT;
    float dot = 0.f, sq = 0.f;
#pragma unroll
    for (int j = 0; j < 16; j++) {
        int k = lane + 32 * j;
        float wv = w[(size_t)k * NCLS + lab];
        dot += e[k] * wv;
        sq  += wv * wv;
    }
#pragma unroll
    for (int o = 16; o; o >>= 1) {
        dot += __shfl_xor_sync(0xffffffffu, dot, o);
        sq  += __shfl_xor_sync(0xffffffffu, sq, o);
    }
    if (lane == 0) {
        float tl = fminf(1.0f, fmaxf(-1.0f, dot * rsqrtf(sq)));
        g_tl[gw] = tl;
        float sint = sqrtf(fmaxf(0.f, 1.0f - tl * tl));
        float ctm = tl * C_COS_M - sint * C_SIN_M;
        g_ctm[gw] = ctm;
        g_ft[gw] = (tl > C_THRESH) ? ctm : (tl - C_MM);
    }
}

// =================== K3: g_t from target logits ===================
__global__ void k_prep() {
    int i = threadIdx.x;  // 512
    float s = g_tl[i];
#pragma unroll
    for (int o = 16; o; o >>= 1) s += __shfl_xor_sync(0xffffffffu, s, o);
    __shared__ float sm[16];
    if ((i & 31) == 0) sm[i >> 5] = s;
    __syncthreads();
    if (i < 16) {
        float v = sm[i];
#pragma unroll
        for (int o = 8; o; o >>= 1) v += __shfl_xor_sync(0x0000ffffu, v, o);
        if (i == 0) g_t = 0.01f * (v / (float)NROW);
    }
}

// =================== K4: fused GEMM (f32 w ingest) + epilogue ===================
// smem: A bf16 [2][16KB] @0, Bbf16 [2][16KB] @32K, f32 staging 32KB @64K  => 96KB
#define SMA(s)  ((s) * 16384)
#define SMBB(s) (32768 + (s) * 16384)
#define SMST    65536
#define SMSZ    98304

__device__ __forceinline__ void load_a(uint32_t sb, int s, int chunk,
                                       const char* ag0, int tid) {
    const char* ag = ag0 + chunk * 128;
    uint32_t as_ = sb + SMA(s);
#pragma unroll
    for (int u = 0; u < 4; u++) {          // 128 rows x 8 segs of 16B
        int i = tid + u * 256;
        int row = i >> 3, seg = i & 7;
        cp16(as_ + sw((uint32_t)(row * 128 + seg * 16)), ag + (size_t)row * 1024 + seg * 16);
    }
}

__device__ __forceinline__ void load_w(uint32_t sb, int chunk,
                                       const float* __restrict__ w, int c0, int tid) {
    // f32 chunk [64 k][128 c], staging rows 512B, 32 segs of 16B, sw-swizzled
    int k0 = chunk * 64;
#pragma unroll
    for (int u = 0; u < 8; u++) {
        int i = tid + u * 256;             // 2048 float4
        int k = i >> 5, seg = i & 31;
        int c = c0 + seg * 4;              // NCLS % 4 == 0 -> float4 all-or-none valid
        int valid = (c < NCLS);
        const float* src = w + (size_t)(k0 + k) * NCLS + (valid ? c : 0);
        cp16z(sb + SMST + sw((uint32_t)(k * 512 + seg * 16)), src, valid ? 16 : 0);
    }
}

__global__ void __launch_bounds__(256, 2) k_gemm(const int* __restrict__ label,
                                                 const float* __restrict__ w) {
    extern __shared__ char smdy[];
    uint32_t sb = s2u(smdy);
    const int tid = threadIdx.x, lane = tid & 31, wid = tid >> 5;
    const int warpM = wid >> 2;            // 0..1
    const int warpN = wid & 3;             // 0..3
    const int r0 = blockIdx.x * BM;
    const int c0 = blockIdx.y * BN;
    const int c8 = (tid & 15) * 8;         // conversion column group
    const int kps = tid >> 4;              // conversion k-pair slot 0..15

    float acc[4][4][4];
#pragma unroll
    for (int a = 0; a < 4; a++)
#pragma unroll
        for (int b = 0; b < 4; b++)
#pragma unroll
            for (int c = 0; c < 4; c++) acc[a][b][c] = 0.f;
    float sq8[8];
#pragma unroll
    for (int j = 0; j < 8; j++) sq8[j] = 0.f;

    const char* ag0 = (const char*)(g_ebf + (size_t)r0 * FEAT);

    load_w(sb, 0, w, c0, tid);
    load_a(sb, 0, 0, ag0, tid);
    asm volatile("cp.async.commit_group;");

#pragma unroll 1
    for (int it = 0; it < NCH; it++) {
        int s = it & 1;
        asm volatile("cp.async.wait_group 0;");
        __syncthreads();

        // ---- convert staging f32 [k][c] -> Bbf[s] bf16 [c][k] + sumsq ----
#pragma unroll
        for (int u = 0; u < 2; u++) {
            int kp = kps + 16 * u;         // 0..31
            int k0 = kp * 2, k1 = k0 + 1;
            float4 x0 = *(const float4*)(smdy + SMST + sw((uint32_t)(k0 * 512 + c8 * 4)));
            float4 x1 = *(const float4*)(smdy + SMST + sw((uint32_t)(k0 * 512 + c8 * 4 + 16)));
            float4 y0 = *(const float4*)(smdy + SMST + sw((uint32_t)(k1 * 512 + c8 * 4)));
            float4 y1 = *(const float4*)(smdy + SMST + sw((uint32_t)(k1 * 512 + c8 * 4 + 16)));
            float xs[8] = {x0.x, x0.y, x0.z, x0.w, x1.x, x1.y, x1.z, x1.w};
            float ys[8] = {y0.x, y0.y, y0.z, y0.w, y1.x, y1.y, y1.z, y1.w};
#pragma unroll
            for (int j = 0; j < 8; j++) {
                sq8[j] += xs[j] * xs[j] + ys[j] * ys[j];
                __nv_bfloat162 p = __floats2bfloat162_rn(xs[j], ys[j]);
                *(__nv_bfloat162*)(smdy + SMBB(s) + sw((uint32_t)((c8 + j) * 128 + k0 * 2))) = p;
            }
        }
        __syncthreads();   // staging free, Bbf[s] ready

        if (it < NCH - 1) {
            load_w(sb, it + 1, w, c0, tid);
            load_a(sb, s ^ 1, it + 1, ag0, tid);
            asm volatile("cp.async.commit_group;");
        }

        // ---- mma on A[s], Bbf[s] (verified round-6 core) ----
        uint32_t aST = sb + SMA(s);
        uint32_t bST = sb + SMBB(s);
#pragma unroll
        for (int ks = 0; ks < 4; ks++) {
            int kb = ks * 32;
            uint32_t af[4][4], bf[2][4];
#pragma unroll
            for (int mt = 0; mt < 4; mt++) {
                int r = warpM * 64 + mt * 16 + (lane & 7) + ((lane >> 3) & 1) * 8;
                int kb2 = kb + ((lane >> 4) & 1) * 16;
                ldsm4(af[mt], aST + sw((uint32_t)(r * 128 + kb2)));
            }
#pragma unroll
            for (int pr = 0; pr < 2; pr++) {
                int r = warpN * 32 + pr * 16 + ((lane >> 4) & 1) * 8 + (lane & 7);
                int kb2 = kb + ((lane >> 3) & 1) * 16;
                ldsm4(bf[pr], bST + sw((uint32_t)(r * 128 + kb2)));
            }
#pragma unroll
            for (int mt = 0; mt < 4; mt++)
#pragma unroll
                for (int nt = 0; nt < 4; nt++)
                    mma16816(acc[mt][nt], af[mt], &bf[nt >> 1][(nt & 1) * 2]);
        }
    }
    __syncthreads();

    // ---- column inv-norms from in-kernel sums ----
    float* sums = (float*)(smdy + SMST);   // [16][128]
#pragma unroll
    for (int j = 0; j < 8; j++) sums[kps * 128 + c8 + j] = sq8[j];
    __syncthreads();

    float* smf = (float*)smdy;
    int*   smi = (int*)smdy;
    // [0..127] invwn, [128..255] ctm, [256..383] ft, [384..511] label,
    // [512..1023] pm[4][128], [1024..1535] ps, [1536..2047] psl
    if (tid < 128) {
        float z = 0.f;
#pragma unroll
        for (int s16 = 0; s16 < 16; s16++) z += sums[s16 * 128 + tid];
        smf[tid] = rsqrtf(z);              // inf on zero-padded cols; masked below
        int r = r0 + tid;
        smf[128 + tid] = g_ctm[r];
        smf[256 + tid] = g_ft[r];
        smi[384 + tid] = label[r];
    }
    __syncthreads();

    const float tad = g_t;
    const int g = lane >> 2, q = lane & 3;
#pragma unroll
    for (int mt = 0; mt < 4; mt++) {
#pragma unroll
        for (int half = 0; half < 2; half++) {
            int rl = warpM * 64 + mt * 16 + g + half * 8;
            float ctm = smf[128 + rl], ft = smf[256 + rl];
            int lab = smi[384 + rl];
            float L[8];
            float mx = -3.0e38f;
#pragma unroll
            for (int nt = 0; nt < 4; nt++) {
#pragma unroll
                for (int b = 0; b < 2; b++) {
                    int cl = warpN * 32 + nt * 8 + q * 2 + b;
                    int c = c0 + cl;
                    float Lv;
                    if (c < NCLS) {
                        float cv = acc[mt][nt][half * 2 + b] * smf[cl];
                        cv = fminf(1.f, fmaxf(-1.f, cv));
                        if (c == lab) {
                            Lv = C_S * ft;
                        } else {
                            if (cv > ctm) cv = cv * (tad + cv);
                            Lv = C_S * cv;
                        }
                        mx = fmaxf(mx, Lv);
                    } else {
                        Lv = -3.0e38f;
                    }
                    L[nt * 2 + b] = Lv;
                }
            }
            mx = fmaxf(mx, __shfl_xor_sync(0xffffffffu, mx, 1));
            mx = fmaxf(mx, __shfl_xor_sync(0xffffffffu, mx, 2));
            float s = 0.f, sl = 0.f;
#pragma unroll
            for (int j = 0; j < 8; j++) {
                if (L[j] > -1.0e38f) { s += __expf(L[j] - mx); sl += L[j]; }
            }
            s  += __shfl_xor_sync(0xffffffffu, s, 1);
            s  += __shfl_xor_sync(0xffffffffu, s, 2);
            sl += __shfl_xor_sync(0xffffffffu, sl, 1);
            sl += __shfl_xor_sync(0xffffffffu, sl, 2);
            if (q == 0) {
                smf[512  + warpN * 128 + rl] = mx;
                smf[1024 + warpN * 128 + rl] = s;
                smf[1536 + warpN * 128 + rl] = sl;
            }
        }
    }
    __syncthreads();

    if (tid < 128) {
        float m = -3.0e38f;
#pragma unroll
        for (int wn = 0; wn < 4; wn++) m = fmaxf(m, smf[512 + wn * 128 + tid]);
        float s = 0.f, sl = 0.f;
#pragma unroll
        for (int wn = 0; wn < 4; wn++) {
            float mw = smf[512 + wn * 128 + tid];
            if (mw > -1.0e38f) s += smf[1024 + wn * 128 + tid] * __expf(mw - m);
            sl += smf[1536 + wn * 128 + tid];
        }
        int slot = (r0 + tid) * CTP + blockIdx.y;
        g_pm[slot] = m;
        g_ps[slot] = s;
        g_psl[slot] = sl;
    }
}

// =================== K5: merge partials per row ===================
__global__ void k_rowreduce() {
    int r = blockIdx.x;
    int tid = threadIdx.x;  // 256
    float m = -3.0e38f, s = 0.f, sl = 0.f;
    for (int ct = tid; ct < CTP; ct += 256) {
        float m2 = g_pm[r * CTP + ct];
        float s2 = g_ps[r * CTP + ct];
        sl += g_psl[r * CTP + ct];
        if (m2 > m) { s = s * __expf(m - m2) + s2; m = m2; }
        else        { s += s2 * __expf(m2 - m); }
    }
    __shared__ float sm_m[256], sm_s[256], sm_sl[256];
    sm_m[tid] = m; sm_s[tid] = s; sm_sl[tid] = sl;
    __syncthreads();
    for (int o = 128; o; o >>= 1) {
        if (tid < o) {
            float m1 = sm_m[tid], s1 = sm_s[tid];
            float m2 = sm_m[tid + o], s2 = sm_s[tid + o];
            float M = fmaxf(m1, m2);
            sm_s[tid] = s1 * __expf(m1 - M) + s2 * __expf(m2 - M);
            sm_m[tid] = M;
            sm_sl[tid] += sm_sl[tid + o];
        }
        __syncthreads();
    }
    if (tid == 0) {
        float LSE = sm_m[0] + logf(sm_s[0]);
        float nll = LSE - C_S * g_ft[r];
        float smooth = LSE - sm_sl[0] / (float)NCLS;
        g_rowloss[r] = (1.0f - C_EPS) * nll + C_EPS * smooth;
    }
}

// =================== K6: mean ===================
__global__ void k_final(float* __restrict__ out) {
    int tid = threadIdx.x;  // 512
    float v = g_rowloss[tid];
#pragma unroll
    for (int o = 16; o; o >>= 1) v += __shfl_xor_sync(0xffffffffu, v, o);
    __shared__ float sm[16];
    if ((tid & 31) == 0) sm[tid >> 5] = v;
    __syncthreads();
    if (tid < 16) {
        float x = sm[tid];
#pragma unroll
        for (int o = 8; o; o >>= 1) x += __shfl_xor_sync(0x0000ffffu, x, o);
        if (tid == 0) out[0] = x / (float)NROW;
    }
}

// ===================================================
extern "C" void kernel_launch(void* const* d_in, const int* in_sizes, int n_in,
                              void* d_out, int out_size) {
    const float* emb = (const float*)d_in[0];
    const float* w = (const float*)d_in[1];
    const int* label = (const int*)d_in[2];
    float* out = (float*)d_out;

    cudaFuncSetAttribute(k_gemm, cudaFuncAttributeMaxDynamicSharedMemorySize, SMSZ);

    k_norm_e<<<NROW, 128>>>(emb);
    k_target<<<64, 256>>>(w, label);
    k_prep<<<1, NROW>>>();
    k_gemm<<<dim3(NRT, NCT), 256, SMSZ>>>(label, w);
    k_rowreduce<<<NROW, 256>>>();
    k_final<<<1, NROW>>>(out);
}

// round 9
// speedup vs baseline: 1.7134x; 1.7134x over previous
#include <cuda_runtime.h>
#include <cuda_bf16.h>
#include <stdint.h>
#include <math.h>

#define FEAT  512
#define NCLS  100000
#define NROW  512
#define BM    128
#define BN    128
#define NCT   782             // class tiles (782*128 = 100096 padded)
#define NRT   4               // row tiles
#define CTP   782
#define NCH   8               // K chunks of 64

#define C_COS_M   0.87758256189037276f
#define C_SIN_M   0.47942553860420301f
#define C_THRESH  (-0.87758256189037276f)
#define C_MM      0.23971276930210156f
#define C_S       64.0f
#define C_EPS     0.1f

// ---- scratch ----
__device__ float          g_e[NROW * FEAT];
__device__ __nv_bfloat16  g_ebf[NROW * FEAT];
__device__ float g_tl[NROW];
__device__ float g_ctm[NROW];
__device__ float g_ft[NROW];
__device__ float g_t;
__device__ float g_pm[NROW * CTP];
__device__ float g_ps[NROW * CTP];
__device__ float g_psl[NROW * CTP];
__device__ float g_rowloss[NROW];

// =================== helpers ===================
__device__ __forceinline__ void cp16(uint32_t dst, const void* src) {
    asm volatile("cp.async.cg.shared.global [%0], [%1], 16;" :: "r"(dst), "l"(src));
}
__device__ __forceinline__ void cp16z(uint32_t dst, const void* src, int nbytes) {
    asm volatile("cp.async.cg.shared.global [%0], [%1], 16, %2;"
                 :: "r"(dst), "l"(src), "r"(nbytes));
}
__device__ __forceinline__ uint32_t s2u(const void* p) {
    uint32_t a;
    asm("{ .reg .u64 t; cvta.to.shared.u64 t, %1; cvt.u32.u64 %0, t; }" : "=r"(a) : "l"(p));
    return a;
}
__device__ __forceinline__ uint32_t sw(uint32_t x) { return x ^ ((x >> 3) & 0x70); }
// B tile [k][c] bf16, 256B rows; 16B-chunk XOR swizzle by k
__device__ __forceinline__ uint32_t bswz(int k, int c) {
    return (uint32_t)(k * 256 + ((((c >> 3) ^ k) & 7) << 4) + ((c >> 3) & 8) * 16 + (c & 7) * 2);
}
__device__ __forceinline__ void ldsm4(uint32_t* a, uint32_t addr) {
    asm volatile("ldmatrix.sync.aligned.m8n8.x4.shared.b16 {%0,%1,%2,%3}, [%4];"
                 : "=r"(a[0]), "=r"(a[1]), "=r"(a[2]), "=r"(a[3]) : "r"(addr));
}
__device__ __forceinline__ void ldsm4t(uint32_t* a, uint32_t addr) {
    asm volatile("ldmatrix.sync.aligned.m8n8.x4.trans.shared.b16 {%0,%1,%2,%3}, [%4];"
                 : "=r"(a[0]), "=r"(a[1]), "=r"(a[2]), "=r"(a[3]) : "r"(addr));
}
__device__ __forceinline__ void mma16816(float* c, const uint32_t* a, const uint32_t* b) {
    asm volatile(
        "mma.sync.aligned.m16n8k16.row.col.f32.bf16.bf16.f32 "
        "{%0,%1,%2,%3}, {%4,%5,%6,%7}, {%8,%9}, {%0,%1,%2,%3};"
        : "+f"(c[0]), "+f"(c[1]), "+f"(c[2]), "+f"(c[3])
        : "r"(a[0]), "r"(a[1]), "r"(a[2]), "r"(a[3]), "r"(b[0]), "r"(b[1]));
}

// =================== K1: row-normalize e ===================
__global__ void k_norm_e(const float* __restrict__ emb) {
    int r = blockIdx.x, t = threadIdx.x;   // 512 x 128
    float v[4], s = 0.f;
#pragma unroll
    for (int i = 0; i < 4; i++) { v[i] = emb[r * FEAT + t + i * 128]; s += v[i] * v[i]; }
#pragma unroll
    for (int o = 16; o; o >>= 1) s += __shfl_xor_sync(0xffffffffu, s, o);
    __shared__ float sm[4];
    if ((t & 31) == 0) sm[t >> 5] = s;
    __syncthreads();
    float inv = rsqrtf(sm[0] + sm[1] + sm[2] + sm[3]);
#pragma unroll
    for (int i = 0; i < 4; i++) {
        float x = v[i] * inv;
        g_e[r * FEAT + t + i * 128] = x;
        g_ebf[r * FEAT + t + i * 128] = __float2bfloat16(x);
    }
}

// =================== K2: target logits + ctm/ft (self-normalizing) ===================
__global__ void k_target(const float* __restrict__ w, const int* __restrict__ label) {
    int gw = (blockIdx.x * blockDim.x + threadIdx.x) >> 5;  // 64 x 256 -> 512 warps
    int lane = threadIdx.x & 31;
    if (gw >= NROW) return;
    int lab = label[gw];
    const float* e = g_e + gw * FEAT;
    float dot = 0.f, sq = 0.f;
#pragma unroll
    for (int j = 0; j < 16; j++) {
        int k = lane + 32 * j;
        float wv = w[(size_t)k * NCLS + lab];
        dot += e[k] * wv;
        sq  += wv * wv;
    }
#pragma unroll
    for (int o = 16; o; o >>= 1) {
        dot += __shfl_xor_sync(0xffffffffu, dot, o);
        sq  += __shfl_xor_sync(0xffffffffu, sq, o);
    }
    if (lane == 0) {
        float tl = fminf(1.0f, fmaxf(-1.0f, dot * rsqrtf(sq)));
        g_tl[gw] = tl;
        float sint = sqrtf(fmaxf(0.f, 1.0f - tl * tl));
        float ctm = tl * C_COS_M - sint * C_SIN_M;
        g_ctm[gw] = ctm;
        g_ft[gw] = (tl > C_THRESH) ? ctm : (tl - C_MM);
    }
}

// =================== K3: g_t from target logits ===================
__global__ void k_prep() {
    int i = threadIdx.x;  // 512
    float s = g_tl[i];
#pragma unroll
    for (int o = 16; o; o >>= 1) s += __shfl_xor_sync(0xffffffffu, s, o);
    __shared__ float sm[16];
    if ((i & 31) == 0) sm[i >> 5] = s;
    __syncthreads();
    if (i < 16) {
        float v = sm[i];
#pragma unroll
        for (int o = 8; o; o >>= 1) v += __shfl_xor_sync(0x0000ffffu, v, o);
        if (i == 0) g_t = 0.01f * (v / (float)NROW);
    }
}

// =================== K4: fused GEMM (f32 w ingest, ldmatrix.trans B) ===================
// smem: A bf16 [2][16KB] @0, Bbf16 [k][c] [2][16KB] @32K, f32 staging 32KB @64K => 96KB
#define SMA(s)  ((s) * 16384)
#define SMBB(s) (32768 + (s) * 16384)
#define SMST    65536
#define SMSZ    98304

__device__ __forceinline__ void load_a(uint32_t sb, int s, int chunk,
                                       const char* ag0, int tid) {
    const char* ag = ag0 + chunk * 128;
    uint32_t as_ = sb + SMA(s);
#pragma unroll
    for (int u = 0; u < 4; u++) {          // 128 rows x 8 segs of 16B
        int i = tid + u * 256;
        int row = i >> 3, seg = i & 7;
        cp16(as_ + sw((uint32_t)(row * 128 + seg * 16)), ag + (size_t)row * 1024 + seg * 16);
    }
}

__device__ __forceinline__ void load_w(uint32_t sb, int chunk,
                                       const float* __restrict__ w, int c0, int tid) {
    // f32 chunk [64 k][128 c] -> staging rows 512B, linear (no swizzle needed)
    int k0 = chunk * 64;
#pragma unroll
    for (int u = 0; u < 8; u++) {
        int i = tid + u * 256;             // 2048 float4
        int k = i >> 5, seg = i & 31;
        int c = c0 + seg * 4;              // NCLS % 4 == 0 -> all-or-none valid
        int valid = (c < NCLS);
        const float* src = w + (size_t)(k0 + k) * NCLS + (valid ? c : 0);
        cp16z(sb + SMST + (uint32_t)(k * 512 + seg * 16), src, valid ? 16 : 0);
    }
}

__global__ void __launch_bounds__(256, 2) k_gemm(const int* __restrict__ label,
                                                 const float* __restrict__ w) {
    extern __shared__ char smdy[];
    uint32_t sb = s2u(smdy);
    const int tid = threadIdx.x, lane = tid & 31, wid = tid >> 5;
    const int warpM = wid >> 2;            // 0..1
    const int warpN = wid & 3;             // 0..3
    const int r0 = blockIdx.x * BM;
    const int c0 = blockIdx.y * BN;
    const int cvc = (tid & 31) * 4;        // conversion column quad
    const int cvk = tid >> 5;              // conversion k slot 0..7

    float acc[4][4][4];
#pragma unroll
    for (int a = 0; a < 4; a++)
#pragma unroll
        for (int b = 0; b < 4; b++)
#pragma unroll
            for (int c = 0; c < 4; c++) acc[a][b][c] = 0.f;
    float sq4[4] = {0.f, 0.f, 0.f, 0.f};

    const char* ag0 = (const char*)(g_ebf + (size_t)r0 * FEAT);

    load_w(sb, 0, w, c0, tid);
    load_a(sb, 0, 0, ag0, tid);
    asm volatile("cp.async.commit_group;");

#pragma unroll 1
    for (int it = 0; it < NCH; it++) {
        int s = it & 1;
        asm volatile("cp.async.wait_group 0;");
        __syncthreads();

        // ---- convert staging f32 [k][c] -> Bbf[s] bf16 [k][c] (no transpose) ----
#pragma unroll
        for (int p = 0; p < 8; p++) {
            int k = cvk + p * 8;
            float4 v = *(const float4*)(smdy + SMST + k * 512 + (tid & 31) * 16);
            sq4[0] += v.x * v.x; sq4[1] += v.y * v.y;
            sq4[2] += v.z * v.z; sq4[3] += v.w * v.w;
            __nv_bfloat162 p0 = __floats2bfloat162_rn(v.x, v.y);
            __nv_bfloat162 p1 = __floats2bfloat162_rn(v.z, v.w);
            uint2 u2;
            u2.x = *(uint32_t*)&p0;
            u2.y = *(uint32_t*)&p1;
            *(uint2*)(smdy + SMBB(s) + bswz(k, cvc)) = u2;
        }
        __syncthreads();   // staging free, Bbf[s] ready

        if (it < NCH - 1) {
            load_w(sb, it + 1, w, c0, tid);
            load_a(sb, s ^ 1, it + 1, ag0, tid);
            asm volatile("cp.async.commit_group;");
        }

        // ---- mma on A[s] (non-trans ldsm), Bbf[s] ([k][c] via ldsm.trans) ----
        uint32_t aST = sb + SMA(s);
        uint32_t bST = sb + SMBB(s);
#pragma unroll
        for (int ks = 0; ks < 4; ks++) {
            uint32_t af[4][4], bf[2][4];
#pragma unroll
            for (int mt = 0; mt < 4; mt++) {
                int r = warpM * 64 + mt * 16 + (lane & 7) + ((lane >> 3) & 1) * 8;
                int kb2 = ks * 32 + ((lane >> 4) & 1) * 16;    // bytes
                ldsm4(af[mt], aST + sw((uint32_t)(r * 128 + kb2)));
            }
#pragma unroll
            for (int pr = 0; pr < 2; pr++) {
                int t = lane >> 3, rr = lane & 7;
                int kk = ks * 16 + (t & 1) * 8 + rr;
                int nn = warpN * 32 + pr * 16 + (t >> 1) * 8;
                ldsm4t(bf[pr], bST + bswz(kk, nn));
            }
#pragma unroll
            for (int mt = 0; mt < 4; mt++)
#pragma unroll
                for (int nt = 0; nt < 4; nt++)
                    mma16816(acc[mt][nt], af[mt], &bf[nt >> 1][(nt & 1) * 2]);
        }
    }
    __syncthreads();

    // ---- column inv-norms from in-kernel sums ----
    float* sums = (float*)(smdy + SMST);   // [8][128]
#pragma unroll
    for (int j = 0; j < 4; j++) sums[cvk * 128 + cvc + j] = sq4[j];
    __syncthreads();

    float* smf = (float*)smdy;
    int*   smi = (int*)smdy;
    // [0..127] invwn, [128..255] ctm, [256..383] ft, [384..511] label,
    // [512..1023] pm[4][128], [1024..1535] ps, [1536..2047] psl
    if (tid < 128) {
        float z = 0.f;
#pragma unroll
        for (int s8 = 0; s8 < 8; s8++) z += sums[s8 * 128 + tid];
        smf[tid] = rsqrtf(z);              // inf on zero-padded cols; masked below
        int r = r0 + tid;
        smf[128 + tid] = g_ctm[r];
        smf[256 + tid] = g_ft[r];
        smi[384 + tid] = label[r];
    }
    __syncthreads();

    const float tad = g_t;
    const int g = lane >> 2, q = lane & 3;
#pragma unroll
    for (int mt = 0; mt < 4; mt++) {
#pragma unroll
        for (int half = 0; half < 2; half++) {
            int rl = warpM * 64 + mt * 16 + g + half * 8;
            float ctm = smf[128 + rl], ft = smf[256 + rl];
            int lab = smi[384 + rl];
            float L[8];
            float mx = -3.0e38f;
#pragma unroll
            for (int nt = 0; nt < 4; nt++) {
#pragma unroll
                for (int b = 0; b < 2; b++) {
                    int cl = warpN * 32 + nt * 8 + q * 2 + b;
                    int c = c0 + cl;
                    float Lv;
                    if (c < NCLS) {
                        float cv = acc[mt][nt][half * 2 + b] * smf[cl];
                        cv = fminf(1.f, fmaxf(-1.f, cv));
                        if (c == lab) {
                            Lv = C_S * ft;
                        } else {
                            if (cv > ctm) cv = cv * (tad + cv);
                            Lv = C_S * cv;
                        }
                        mx = fmaxf(mx, Lv);
                    } else {
                        Lv = -3.0e38f;
                    }
                    L[nt * 2 + b] = Lv;
                }
            }
            mx = fmaxf(mx, __shfl_xor_sync(0xffffffffu, mx, 1));
            mx = fmaxf(mx, __shfl_xor_sync(0xffffffffu, mx, 2));
            float s = 0.f, sl = 0.f;
#pragma unroll
            for (int j = 0; j < 8; j++) {
                if (L[j] > -1.0e38f) { s += __expf(L[j] - mx); sl += L[j]; }
            }
            s  += __shfl_xor_sync(0xffffffffu, s, 1);
            s  += __shfl_xor_sync(0xffffffffu, s, 2);
            sl += __shfl_xor_sync(0xffffffffu, sl, 1);
            sl += __shfl_xor_sync(0xffffffffu, sl, 2);
            if (q == 0) {
                smf[512  + warpN * 128 + rl] = mx;
                smf[1024 + warpN * 128 + rl] = s;
                smf[1536 + warpN * 128 + rl] = sl;
            }
        }
    }
    __syncthreads();

    if (tid < 128) {
        float m = -3.0e38f;
#pragma unroll
        for (int wn = 0; wn < 4; wn++) m = fmaxf(m, smf[512 + wn * 128 + tid]);
        float s = 0.f, sl = 0.f;
#pragma unroll
        for (int wn = 0; wn < 4; wn++) {
            float mw = smf[512 + wn * 128 + tid];
            if (mw > -1.0e38f) s += smf[1024 + wn * 128 + tid] * __expf(mw - m);
            sl += smf[1536 + wn * 128 + tid];
        }
        int slot = (r0 + tid) * CTP + blockIdx.y;
        g_pm[slot] = m;
        g_ps[slot] = s;
        g_psl[slot] = sl;
    }
}

// =================== K5: merge partials per row ===================
__global__ void k_rowreduce() {
    int r = blockIdx.x;
    int tid = threadIdx.x;  // 256
    float m = -3.0e38f, s = 0.f, sl = 0.f;
    for (int ct = tid; ct < CTP; ct += 256) {
        float m2 = g_pm[r * CTP + ct];
        float s2 = g_ps[r * CTP + ct];
        sl += g_psl[r * CTP + ct];
        if (m2 > m) { s = s * __expf(m - m2) + s2; m = m2; }
        else        { s += s2 * __expf(m2 - m); }
    }
    __shared__ float sm_m[256], sm_s[256], sm_sl[256];
    sm_m[tid] = m; sm_s[tid] = s; sm_sl[tid] = sl;
    __syncthreads();
    for (int o = 128; o; o >>= 1) {
        if (tid < o) {
            float m1 = sm_m[tid], s1 = sm_s[tid];
            float m2 = sm_m[tid + o], s2 = sm_s[tid + o];
            float M = fmaxf(m1, m2);
            sm_s[tid] = s1 * __expf(m1 - M) + s2 * __expf(m2 - M);
            sm_m[tid] = M;
            sm_sl[tid] += sm_sl[tid + o];
        }
        __syncthreads();
    }
    if (tid == 0) {
        float LSE = sm_m[0] + logf(sm_s[0]);
        float nll = LSE - C_S * g_ft[r];
        float smooth = LSE - sm_sl[0] / (float)NCLS;
        g_rowloss[r] = (1.0f - C_EPS) * nll + C_EPS * smooth;
    }
}

// =================== K6: mean ===================
__global__ void k_final(float* __restrict__ out) {
    int tid = threadIdx.x;  // 512
    float v = g_rowloss[tid];
#pragma unroll
    for (int o = 16; o; o >>= 1) v += __shfl_xor_sync(0xffffffffu, v, o);
    __shared__ float sm[16];
    if ((tid & 31) == 0) sm[tid >> 5] = v;
    __syncthreads();
    if (tid < 16) {
        float x = sm[tid];
#pragma unroll
        for (int o = 8; o; o >>= 1) x += __shfl_xor_sync(0x0000ffffu, x, o);
        if (tid == 0) out[0] = x / (float)NROW;
    }
}

// ===================================================
extern "C" void kernel_launch(void* const* d_in, const int* in_sizes, int n_in,
                              void* d_out, int out_size) {
    const float* emb = (const float*)d_in[0];
    const float* w = (const float*)d_in[1];
    const int* label = (const int*)d_in[2];
    float* out = (float*)d_out;

    cudaFuncSetAttribute(k_gemm, cudaFuncAttributeMaxDynamicSharedMemorySize, SMSZ);

    k_norm_e<<<NROW, 128>>>(emb);
    k_target<<<64, 256>>>(w, label);
    k_prep<<<1, NROW>>>();
    k_gemm<<<dim3(NRT, NCT), 256, SMSZ>>>(label, w);
    k_rowreduce<<<NROW, 256>>>();
    k_final<<<1, NROW>>>(out);
}